// round 5
// baseline (speedup 1.0000x reference)
#include <cuda_runtime.h>

#define NN 100000
#define EE 1600000
#define FT 96
#define TT 12

// ---------------- scratch (device globals; no runtime allocation) ----------------
__device__ float g_wx[(size_t)NN * FT];   // weighted features, node-major [n][j], j = f*12+t
__device__ float g_agg[(size_t)FT * NN];  // aggregated features, TRANSPOSED [j][n]
__device__ float g_deg[NN];
__device__ float g_dis[NN];
__device__ float g_M[3 * 8 * 32];         // fused input-projection weights (conv_w @ lin_w_top) z,r,h
__device__ float g_gb[3 * 32];            // fused biases
__device__ float g_probs[TT];             // softmax(att)

__device__ __forceinline__ float sigf(float x) { return 1.0f / (1.0f + __expf(-x)); }

// ---------------- fused weight precompute + softmax(att) ----------------
__global__ void k_precompute(const float* czw, const float* czb, const float* lzw, const float* lzb,
                             const float* crw, const float* crb, const float* lrw, const float* lrb,
                             const float* chw, const float* chb, const float* lhw, const float* lhb,
                             const float* att)
{
    int tid = threadIdx.x;           // 256 threads
    int f = tid >> 5, l = tid & 31;  // f in [0,8), l in [0,32)
#pragma unroll
    for (int g = 0; g < 3; g++) {
        const float* CW = (g == 0) ? czw : (g == 1) ? crw : chw;
        const float* CB = (g == 0) ? czb : (g == 1) ? crb : chb;
        const float* LW = (g == 0) ? lzw : (g == 1) ? lrw : lhw;
        const float* LB = (g == 0) ? lzb : (g == 1) ? lrb : lhb;
        float m = 0.f;
        for (int k = 0; k < 32; k++) m += CW[f * 32 + k] * LW[k * 32 + l];
        g_M[g * 256 + f * 32 + l] = m;
        if (f == 0) {
            float b = LB[l];
            for (int k = 0; k < 32; k++) b += CB[k] * LW[k * 32 + l];
            g_gb[g * 32 + l] = b;
        }
    }
    if (tid < TT) {
        float mx = -1e30f;
        for (int t = 0; t < TT; t++) mx = fmaxf(mx, att[t]);
        float s = 0.f;
        for (int t = 0; t < TT; t++) s += __expf(att[t] - mx);
        g_probs[tid] = __expf(att[tid] - mx) / s;
    }
}

// ---------------- wx = x * sigmoid(x_flat @ mlp_w + mlp_b); also reset deg ----------------
__global__ void k_wx(const float* __restrict__ x, const float* __restrict__ mlp_w,
                     const float* __restrict__ mlp_b)
{
    __shared__ float sW[TT * FT];  // transposed: [t][j]
    __shared__ float sB[TT];
    int tid = threadIdx.x;  // 256
    for (int i = tid; i < TT * FT; i += 256) {
        int t = i / FT, j = i % FT;
        sW[i] = mlp_w[j * TT + t];
    }
    if (tid < TT) sB[tid] = mlp_b[tid];
    __syncthreads();

    int n = blockIdx.x * 8 + (tid >> 5);
    if (n >= NN) return;
    int lane = tid & 31;
    const float* xr = x + (size_t)n * FT;
    float x0 = xr[lane], x1 = xr[lane + 32], x2 = xr[lane + 64];

    float p[TT];
#pragma unroll
    for (int t = 0; t < TT; t++)
        p[t] = x0 * sW[t * FT + lane] + x1 * sW[t * FT + lane + 32] + x2 * sW[t * FT + lane + 64];
#pragma unroll
    for (int off = 16; off; off >>= 1) {
#pragma unroll
        for (int t = 0; t < TT; t++) p[t] += __shfl_xor_sync(0xffffffffu, p[t], off);
    }
    float* wr = g_wx + (size_t)n * FT;
    int j0 = lane % 12, j1 = (lane + 32) % 12, j2 = (lane + 64) % 12;
    wr[lane]      = x0 * sigf(p[j0] + sB[j0]);
    wr[lane + 32] = x1 * sigf(p[j1] + sB[j1]);
    wr[lane + 64] = x2 * sigf(p[j2] + sB[j2]);
    if (lane == 0) g_deg[n] = 1.0f;  // self-loop weight; rewritten every call (replay safe)
}

// ---------------- degree accumulation ----------------
__global__ void k_deg(const int* __restrict__ ei, const float* __restrict__ ew)
{
    int e = blockIdx.x * 256 + threadIdx.x;
    if (e < EE) atomicAdd(&g_deg[ei[EE + e]], ew[e]);
}

// ---------------- self-loop init of agg (overwrites -> replay safe) + dis = rsqrt(deg) ----------------
__global__ void k_selfinit()
{
    int n = blockIdx.x * 8 + (threadIdx.x >> 5);
    if (n >= NN) return;
    int lane = threadIdx.x & 31;
    float d = g_deg[n];        // >= 1 always (self loop)
    float inv = 1.0f / d;      // self-loop norm = dis^2 = 1/deg
    const float* wr = g_wx + (size_t)n * FT;
#pragma unroll
    for (int q = 0; q < 3; q++) {
        int j = lane + 32 * q;
        g_agg[(size_t)j * NN + n] = wr[j] * inv;
    }
    if (lane == 0) g_dis[n] = rsqrtf(d);
}

// ---------------- edge scatter-add: agg[dst] += norm * wx[src] (96 channels, warp/edge) ----------------
__global__ void k_agg(const int* __restrict__ ei, const float* __restrict__ ew)
{
    int e = blockIdx.x * 8 + (threadIdx.x >> 5);
    if (e >= EE) return;
    int s = ei[e], d = ei[EE + e];
    float nrm = g_dis[s] * ew[e] * g_dis[d];
    int lane = threadIdx.x & 31;
    const float* wr = g_wx + (size_t)s * FT;
#pragma unroll
    for (int q = 0; q < 3; q++) {
        int j = lane + 32 * q;
        atomicAdd(&g_agg[(size_t)j * NN + d], nrm * wr[j]);
    }
}

// ---------------- per-node GRU recurrence + output head ----------------
// 4 threads per node (quad within a warp); each thread owns 8 of the 32 hidden
// channels. Cross-channel H values come via quad-local __shfl_sync. This keeps
// the per-thread live set ~50 floats -> no spills, no local memory.
__global__ void __launch_bounds__(128) k_gru(const float* __restrict__ lzw, const float* __restrict__ lrw,
                                             const float* __restrict__ lhw, const float* __restrict__ out_w,
                                             const float* __restrict__ out_b, float* __restrict__ out)
{
    __shared__ float sM[3 * 8 * 32];    // fused input projections (z,r,h)
    __shared__ float sW2[3 * 32 * 32];  // H-projections: rows 32..63 of lin weights (z,r,h)
    __shared__ float sb[3 * 32];        // fused biases
    __shared__ float sOw[32 * TT];
    __shared__ float sOb[TT];
    __shared__ float sP[TT];

    int tid = threadIdx.x;  // 128
    for (int i = tid; i < 768; i += 128) sM[i] = g_M[i];
    for (int i = tid; i < 1024; i += 128) {
        sW2[i]        = lzw[1024 + i];
        sW2[1024 + i] = lrw[1024 + i];
        sW2[2048 + i] = lhw[1024 + i];
    }
    for (int i = tid; i < 96; i += 128) sb[i] = g_gb[i];
    for (int i = tid; i < 32 * TT; i += 128) sOw[i] = out_w[i];
    if (tid < TT) { sOb[tid] = out_b[tid]; sP[tid] = g_probs[tid]; }
    __syncthreads();

    // grid is exactly NN*4 threads (3125 * 128); no inactive lanes.
    int lane = tid & 31;
    int q = lane & 3;                       // quad slot -> channel block
    int c0 = q * 8;                         // first owned channel
    int n = (blockIdx.x * 128 + tid) >> 2;  // node id
    int qbase = lane & ~3;                  // first lane of this quad

    float H[8], Ha[8];
#pragma unroll
    for (int j = 0; j < 8; j++) { H[j] = 0.f; Ha[j] = 0.f; }

#pragma unroll 1
    for (int t = 0; t < TT; t++) {
        float a[8];
#pragma unroll
        for (int f = 0; f < 8; f++) a[f] = g_agg[(size_t)(f * TT + t) * NN + n];

        // ---- Z and R gates together (both use old H -> share shuffles) ----
        float z[8], r[8];
#pragma unroll
        for (int j = 0; j < 8; j++) { z[j] = sb[c0 + j]; r[j] = sb[32 + c0 + j]; }
#pragma unroll
        for (int f = 0; f < 8; f++) {
            float af = a[f];
#pragma unroll
            for (int j = 0; j < 8; j++) {
                z[j] += af * sM[f * 32 + c0 + j];
                r[j] += af * sM[256 + f * 32 + c0 + j];
            }
        }
#pragma unroll
        for (int k = 0; k < 32; k++) {
            float hk = __shfl_sync(0xffffffffu, H[k & 7], qbase | (k >> 3));
#pragma unroll
            for (int j = 0; j < 8; j++) {
                z[j] += hk * sW2[k * 32 + c0 + j];
                r[j] += hk * sW2[1024 + k * 32 + c0 + j];
            }
        }
#pragma unroll
        for (int j = 0; j < 8; j++) r[j] = sigf(r[j]) * H[j];  // r becomes H*R

        // ---- candidate gate (uses H*R) ----
        float hc[8];
#pragma unroll
        for (int j = 0; j < 8; j++) hc[j] = sb[64 + c0 + j];
#pragma unroll
        for (int f = 0; f < 8; f++) {
            float af = a[f];
#pragma unroll
            for (int j = 0; j < 8; j++) hc[j] += af * sM[512 + f * 32 + c0 + j];
        }
#pragma unroll
        for (int k = 0; k < 32; k++) {
            float hrk = __shfl_sync(0xffffffffu, r[k & 7], qbase | (k >> 3));
#pragma unroll
            for (int j = 0; j < 8; j++) hc[j] += hrk * sW2[2048 + k * 32 + c0 + j];
        }

        float pt = sP[t];
#pragma unroll
        for (int j = 0; j < 8; j++) {
            float zz = sigf(z[j]);
            float ht = tanhf(hc[j]);
            H[j] = zz * H[j] + (1.0f - zz) * ht;
            Ha[j] += pt * H[j];
        }
    }

    // ---- output head: relu(Ha) @ out_w + out_b, quad-reduced ----
#pragma unroll
    for (int j = 0; j < 8; j++) Ha[j] = fmaxf(Ha[j], 0.f);
    float o[TT];
#pragma unroll
    for (int t = 0; t < TT; t++) {
        float acc = 0.f;
#pragma unroll
        for (int j = 0; j < 8; j++) acc += Ha[j] * sOw[(c0 + j) * TT + t];
        acc += __shfl_xor_sync(0xffffffffu, acc, 1);
        acc += __shfl_xor_sync(0xffffffffu, acc, 2);
        o[t] = acc;
    }
    if (q == 0) {
#pragma unroll
        for (int t = 0; t < TT; t++) out[(size_t)n * TT + t] = o[t] + sOb[t];
    }
}

// ---------------- launch ----------------
extern "C" void kernel_launch(void* const* d_in, const int* in_sizes, int n_in,
                              void* d_out, int out_size)
{
    const float* x     = (const float*)d_in[0];
    const int*   ei    = (const int*)d_in[1];
    const float* ew    = (const float*)d_in[2];
    const float* mlp_w = (const float*)d_in[3];
    const float* mlp_b = (const float*)d_in[4];
    const float* att   = (const float*)d_in[5];
    const float* czw   = (const float*)d_in[6];
    const float* czb   = (const float*)d_in[7];
    const float* lzw   = (const float*)d_in[8];
    const float* lzb   = (const float*)d_in[9];
    const float* crw   = (const float*)d_in[10];
    const float* crb   = (const float*)d_in[11];
    const float* lrw   = (const float*)d_in[12];
    const float* lrb   = (const float*)d_in[13];
    const float* chw   = (const float*)d_in[14];
    const float* chb   = (const float*)d_in[15];
    const float* lhw   = (const float*)d_in[16];
    const float* lhb   = (const float*)d_in[17];
    const float* ow    = (const float*)d_in[18];
    const float* ob    = (const float*)d_in[19];
    float* out = (float*)d_out;

    k_precompute<<<1, 256>>>(czw, czb, lzw, lzb, crw, crb, lrw, lrb, chw, chb, lhw, lhb, att);
    k_wx<<<(NN + 7) / 8, 256>>>(x, mlp_w, mlp_b);
    k_deg<<<(EE + 255) / 256, 256>>>(ei, ew);
    k_selfinit<<<(NN + 7) / 8, 256>>>();
    k_agg<<<(EE + 7) / 8, 256>>>(ei, ew);
    k_gru<<<(NN * 4) / 128, 128>>>(lzw, lrw, lhw, ow, ob, out);
}

// round 6
// speedup vs baseline: 1.7488x; 1.7488x over previous
#include <cuda_runtime.h>

#define NN 100000
#define EE 1600000
#define FT 96
#define TT 12

// ---------------- scratch (device globals; no runtime allocation) ----------------
__device__ float g_wx[(size_t)NN * FT];   // weighted features, node-major [n][j], j = f*12+t
__device__ float g_agg[(size_t)NN * FT];  // aggregated features, node-major [n][j] (for v4 atomics)
__device__ float g_deg[NN];
__device__ float g_dis[NN];
__device__ float g_M[3 * 8 * 32];         // fused input-projection weights (conv_w @ lin_w_top) z,r,h
__device__ float g_gb[3 * 32];            // fused biases
__device__ float g_probs[TT];             // softmax(att)

__device__ __forceinline__ float sigf(float x) { return 1.0f / (1.0f + __expf(-x)); }

// ---------------- fused weight precompute + softmax(att) ----------------
__global__ void k_precompute(const float* czw, const float* czb, const float* lzw, const float* lzb,
                             const float* crw, const float* crb, const float* lrw, const float* lrb,
                             const float* chw, const float* chb, const float* lhw, const float* lhb,
                             const float* att)
{
    int tid = threadIdx.x;           // 256 threads
    int f = tid >> 5, l = tid & 31;  // f in [0,8), l in [0,32)
#pragma unroll
    for (int g = 0; g < 3; g++) {
        const float* CW = (g == 0) ? czw : (g == 1) ? crw : chw;
        const float* CB = (g == 0) ? czb : (g == 1) ? crb : chb;
        const float* LW = (g == 0) ? lzw : (g == 1) ? lrw : lhw;
        const float* LB = (g == 0) ? lzb : (g == 1) ? lrb : lhb;
        float m = 0.f;
        for (int k = 0; k < 32; k++) m += CW[f * 32 + k] * LW[k * 32 + l];
        g_M[g * 256 + f * 32 + l] = m;
        if (f == 0) {
            float b = LB[l];
            for (int k = 0; k < 32; k++) b += CB[k] * LW[k * 32 + l];
            g_gb[g * 32 + l] = b;
        }
    }
    if (tid < TT) {
        float mx = -1e30f;
        for (int t = 0; t < TT; t++) mx = fmaxf(mx, att[t]);
        float s = 0.f;
        for (int t = 0; t < TT; t++) s += __expf(att[t] - mx);
        g_probs[tid] = __expf(att[tid] - mx) / s;
    }
}

// ---------------- wx = x * sigmoid(x_flat @ mlp_w + mlp_b); also reset deg ----------------
__global__ void k_wx(const float* __restrict__ x, const float* __restrict__ mlp_w,
                     const float* __restrict__ mlp_b)
{
    __shared__ float sW[TT * FT];  // transposed: [t][j]
    __shared__ float sB[TT];
    int tid = threadIdx.x;  // 256
    for (int i = tid; i < TT * FT; i += 256) {
        int t = i / FT, j = i % FT;
        sW[i] = mlp_w[j * TT + t];
    }
    if (tid < TT) sB[tid] = mlp_b[tid];
    __syncthreads();

    int n = blockIdx.x * 8 + (tid >> 5);
    if (n >= NN) return;
    int lane = tid & 31;
    const float* xr = x + (size_t)n * FT;
    float x0 = xr[lane], x1 = xr[lane + 32], x2 = xr[lane + 64];

    float p[TT];
#pragma unroll
    for (int t = 0; t < TT; t++)
        p[t] = x0 * sW[t * FT + lane] + x1 * sW[t * FT + lane + 32] + x2 * sW[t * FT + lane + 64];
#pragma unroll
    for (int off = 16; off; off >>= 1) {
#pragma unroll
        for (int t = 0; t < TT; t++) p[t] += __shfl_xor_sync(0xffffffffu, p[t], off);
    }
    float* wr = g_wx + (size_t)n * FT;
    int j0 = lane % 12, j1 = (lane + 32) % 12, j2 = (lane + 64) % 12;
    wr[lane]      = x0 * sigf(p[j0] + sB[j0]);
    wr[lane + 32] = x1 * sigf(p[j1] + sB[j1]);
    wr[lane + 64] = x2 * sigf(p[j2] + sB[j2]);
    if (lane == 0) g_deg[n] = 1.0f;  // self-loop weight; rewritten every call (replay safe)
}

// ---------------- degree accumulation ----------------
__global__ void k_deg(const int* __restrict__ ei, const float* __restrict__ ew)
{
    int e = blockIdx.x * 256 + threadIdx.x;
    if (e < EE) atomicAdd(&g_deg[ei[EE + e]], ew[e]);
}

// ---------------- self-loop init of agg (node-major, overwrite -> replay safe) + dis ----------------
__global__ void k_selfinit()
{
    int n = blockIdx.x * 8 + (threadIdx.x >> 5);
    if (n >= NN) return;
    int lane = threadIdx.x & 31;
    float d = g_deg[n];        // >= 1 always (self loop)
    float inv = 1.0f / d;      // self-loop norm = dis^2 = 1/deg
    const float* wr = g_wx + (size_t)n * FT;
    float* ar = g_agg + (size_t)n * FT;
#pragma unroll
    for (int q = 0; q < 3; q++) {
        int j = lane + 32 * q;
        ar[j] = wr[j] * inv;
    }
    if (lane == 0) g_dis[n] = rsqrtf(d);
}

// ---------------- edge scatter-add via vector atomics ----------------
// 4 edges per warp; 8 lanes per edge; each lane does 3 float4 RED ops.
// 24 v4-REDs per edge vs 96 scalar atomics before (4x fewer instructions).
__global__ void k_agg(const int* __restrict__ ei, const float* __restrict__ ew)
{
    int warp = blockIdx.x * (blockDim.x >> 5) + (threadIdx.x >> 5);
    int lane = threadIdx.x & 31;
    int e = warp * 4 + (lane >> 3);
    if (e >= EE) return;
    int s = ei[e], d = ei[EE + e];
    float nrm = g_dis[s] * ew[e] * g_dis[d];
    const float4* wr = (const float4*)(g_wx + (size_t)s * FT);
    float4* ar = (float4*)(g_agg + (size_t)d * FT);
    int c = lane & 7;  // float4 chunk within group
#pragma unroll
    for (int q = 0; q < 3; q++) {
        float4 v = wr[c + 8 * q];
        v.x *= nrm; v.y *= nrm; v.z *= nrm; v.w *= nrm;
        asm volatile("red.global.add.v4.f32 [%0], {%1, %2, %3, %4};"
                     :: "l"(ar + c + 8 * q), "f"(v.x), "f"(v.y), "f"(v.z), "f"(v.w)
                     : "memory");
    }
}

// ---------------- per-node GRU recurrence + output head ----------------
// 4 threads per node; each owns 8 of 32 hidden channels. agg tile staged in smem
// (node-major global -> coalesced; pad-100 stride -> conflict-free quad reads).
__global__ void __launch_bounds__(128) k_gru(const float* __restrict__ lzw, const float* __restrict__ lrw,
                                             const float* __restrict__ lhw, const float* __restrict__ out_w,
                                             const float* __restrict__ out_b, float* __restrict__ out)
{
    __shared__ float sM[3 * 8 * 32];    // fused input projections (z,r,h)
    __shared__ float sW2[3 * 32 * 32];  // H-projections: rows 32..63 of lin weights (z,r,h)
    __shared__ float sb[3 * 32];        // fused biases
    __shared__ float sOw[32 * TT];
    __shared__ float sOb[TT];
    __shared__ float sP[TT];
    __shared__ float sA[32 * 100];      // 32-node agg tile, stride 100 (conflict-free)

    int tid = threadIdx.x;  // 128
    for (int i = tid; i < 768; i += 128) sM[i] = g_M[i];
    for (int i = tid; i < 1024; i += 128) {
        sW2[i]        = lzw[1024 + i];
        sW2[1024 + i] = lrw[1024 + i];
        sW2[2048 + i] = lhw[1024 + i];
    }
    for (int i = tid; i < 96; i += 128) sb[i] = g_gb[i];
    for (int i = tid; i < 32 * TT; i += 128) sOw[i] = out_w[i];
    if (tid < TT) { sOb[tid] = out_b[tid]; sP[tid] = g_probs[tid]; }

    int base = blockIdx.x * 32;  // first node of this block (grid covers NN exactly)
    for (int i = tid; i < 32 * FT; i += 128) {
        int nl = i / FT, j = i % FT;
        sA[nl * 100 + j] = g_agg[(size_t)(base + nl) * FT + j];
    }
    __syncthreads();

    int lane = tid & 31;
    int q = lane & 3;           // quad slot -> channel block
    int c0 = q * 8;             // first owned channel
    int nl = tid >> 2;          // local node (0..31)
    int qbase = lane & ~3;      // first lane of this quad
    const float* aRow = sA + nl * 100;

    float H[8], Ha[8];
#pragma unroll
    for (int j = 0; j < 8; j++) { H[j] = 0.f; Ha[j] = 0.f; }

#pragma unroll 1
    for (int t = 0; t < TT; t++) {
        float a[8];
#pragma unroll
        for (int f = 0; f < 8; f++) a[f] = aRow[f * TT + t];

        // ---- Z and R gates together (both use old H -> share shuffles) ----
        float z[8], r[8];
#pragma unroll
        for (int j = 0; j < 8; j++) { z[j] = sb[c0 + j]; r[j] = sb[32 + c0 + j]; }
#pragma unroll
        for (int f = 0; f < 8; f++) {
            float af = a[f];
#pragma unroll
            for (int j = 0; j < 8; j++) {
                z[j] += af * sM[f * 32 + c0 + j];
                r[j] += af * sM[256 + f * 32 + c0 + j];
            }
        }
#pragma unroll
        for (int k = 0; k < 32; k++) {
            float hk = __shfl_sync(0xffffffffu, H[k & 7], qbase | (k >> 3));
#pragma unroll
            for (int j = 0; j < 8; j++) {
                z[j] += hk * sW2[k * 32 + c0 + j];
                r[j] += hk * sW2[1024 + k * 32 + c0 + j];
            }
        }
#pragma unroll
        for (int j = 0; j < 8; j++) r[j] = sigf(r[j]) * H[j];  // r becomes H*R

        // ---- candidate gate (uses H*R) ----
        float hc[8];
#pragma unroll
        for (int j = 0; j < 8; j++) hc[j] = sb[64 + c0 + j];
#pragma unroll
        for (int f = 0; f < 8; f++) {
            float af = a[f];
#pragma unroll
            for (int j = 0; j < 8; j++) hc[j] += af * sM[512 + f * 32 + c0 + j];
        }
#pragma unroll
        for (int k = 0; k < 32; k++) {
            float hrk = __shfl_sync(0xffffffffu, r[k & 7], qbase | (k >> 3));
#pragma unroll
            for (int j = 0; j < 8; j++) hc[j] += hrk * sW2[2048 + k * 32 + c0 + j];
        }

        float pt = sP[t];
#pragma unroll
        for (int j = 0; j < 8; j++) {
            float zz = sigf(z[j]);
            float ht = tanhf(hc[j]);
            H[j] = zz * H[j] + (1.0f - zz) * ht;
            Ha[j] += pt * H[j];
        }
    }

    // ---- output head: relu(Ha) @ out_w + out_b, quad-reduced, smem-staged store ----
#pragma unroll
    for (int j = 0; j < 8; j++) Ha[j] = fmaxf(Ha[j], 0.f);
    float o[TT];
#pragma unroll
    for (int t = 0; t < TT; t++) {
        float acc = 0.f;
#pragma unroll
        for (int j = 0; j < 8; j++) acc += Ha[j] * sOw[(c0 + j) * TT + t];
        acc += __shfl_xor_sync(0xffffffffu, acc, 1);
        acc += __shfl_xor_sync(0xffffffffu, acc, 2);
        o[t] = acc + sOb[t];
    }
    __syncthreads();  // everyone done reading sA -> reuse as output stage
    if (q == 0) {
#pragma unroll
        for (int t = 0; t < TT; t++) sA[nl * 13 + t] = o[t];
    }
    __syncthreads();
    for (int i = tid; i < 32 * TT; i += 128) {
        int row = i / TT, c = i % TT;
        out[(size_t)(base + row) * TT + c] = sA[row * 13 + c];
    }
}

// ---------------- launch ----------------
extern "C" void kernel_launch(void* const* d_in, const int* in_sizes, int n_in,
                              void* d_out, int out_size)
{
    const float* x     = (const float*)d_in[0];
    const int*   ei    = (const int*)d_in[1];
    const float* ew    = (const float*)d_in[2];
    const float* mlp_w = (const float*)d_in[3];
    const float* mlp_b = (const float*)d_in[4];
    const float* att   = (const float*)d_in[5];
    const float* czw   = (const float*)d_in[6];
    const float* czb   = (const float*)d_in[7];
    const float* lzw   = (const float*)d_in[8];
    const float* lzb   = (const float*)d_in[9];
    const float* crw   = (const float*)d_in[10];
    const float* crb   = (const float*)d_in[11];
    const float* lrw   = (const float*)d_in[12];
    const float* lrb   = (const float*)d_in[13];
    const float* chw   = (const float*)d_in[14];
    const float* chb   = (const float*)d_in[15];
    const float* lhw   = (const float*)d_in[16];
    const float* lhb   = (const float*)d_in[17];
    const float* ow    = (const float*)d_in[18];
    const float* ob    = (const float*)d_in[19];
    float* out = (float*)d_out;

    k_precompute<<<1, 256>>>(czw, czb, lzw, lzb, crw, crb, lrw, lrb, chw, chb, lhw, lhb, att);
    k_wx<<<(NN + 7) / 8, 256>>>(x, mlp_w, mlp_b);
    k_deg<<<(EE + 255) / 256, 256>>>(ei, ew);
    k_selfinit<<<(NN + 7) / 8, 256>>>();
    // 4 edges per warp -> EE/4 warps; 8 warps (256 threads) per block
    k_agg<<<(EE / 4 + 7) / 8, 256>>>(ei, ew);
    k_gru<<<(NN * 4) / 128, 128>>>(lzw, lrw, lhw, ow, ob, out);
}